// round 4
// baseline (speedup 1.0000x reference)
#include <cuda_runtime.h>
#include <math.h>

#define BB 64
#define LL 64
#define GRID 128
#define TPB 256
#define NSLOT 128                    // 64 leaf slots + 63 candidate slots + spare
#define NST (BB*NSLOT*512)           // 16 MB per array

__device__ float g_H[NST];           // unified value/candidate storage (h)
__device__ float g_C[NST];           // unified value/candidate storage (c)
__device__ float g_cwp[128*128];     // cw partials: [rowid][block]
__device__ float g_cw0[BB*63];       // initial pair cw
__device__ unsigned g_barrier;

__device__ __forceinline__ float sigm(float x){ return 1.0f/(1.0f+expf(-x)); }

// packed fp32x2 FMA: 2 MACs/instr (scalar FFMA is half-rate on sm_103a)
__device__ __forceinline__ void ffma2(float2 &acc, float2 a, float2 b){
    asm("fma.rn.f32x2 %0, %1, %2, %0;"
        : "+l"(reinterpret_cast<unsigned long long&>(acc))
        : "l"(reinterpret_cast<unsigned long long&>(a)),
          "l"(reinterpret_cast<unsigned long long&>(b)));
}

// release/acquire grid barrier (all GRID blocks co-resident: 1 block/SM)
__device__ __forceinline__ void grid_barrier(unsigned target){
    __syncthreads();
    if (threadIdx.x == 0){
        asm volatile("red.release.gpu.global.add.u32 [%0], 1;"
                     :: "l"(&g_barrier) : "memory");
        unsigned v;
        do {
            asm volatile("ld.acquire.gpu.global.u32 %0, [%1];"
                         : "=r"(v) : "l"(&g_barrier) : "memory");
        } while (v < target);
    }
    __syncthreads();
}

// ---------------------------------------------------------------------------
// Word GEMM: state = x @ w_word^T + b_word -> leaf slots 0..63
// ---------------------------------------------------------------------------
__global__ __launch_bounds__(256) void word_gemm(
    const float* __restrict__ x, const float* __restrict__ w,
    const float* __restrict__ bias)
{
    __shared__ float As[64][33];
    __shared__ float Ws[64][33];
    int tid = threadIdx.x;
    int tx = tid & 15, ty = tid >> 4;
    int m0 = blockIdx.y * 64;
    int c0 = blockIdx.x * 64;
    float acc[4][4] = {};

    for (int k0 = 0; k0 < 512; k0 += 32) {
        #pragma unroll
        for (int t = tid; t < 64 * 32; t += 256) {
            int r = t >> 5, kk = t & 31;
            As[r][kk] = x[(m0 + r) * 512 + k0 + kk];
            Ws[r][kk] = w[(c0 + r) * 512 + k0 + kk];
        }
        __syncthreads();
        #pragma unroll
        for (int kk = 0; kk < 32; kk++) {
            float a[4], b[4];
            #pragma unroll
            for (int r = 0; r < 4; r++) a[r] = As[ty * 4 + r][kk];
            #pragma unroll
            for (int cc = 0; cc < 4; cc++) b[cc] = Ws[tx * 4 + cc][kk];
            #pragma unroll
            for (int r = 0; r < 4; r++)
                #pragma unroll
                for (int cc = 0; cc < 4; cc++)
                    acc[r][cc] += a[r] * b[cc];
        }
        __syncthreads();
    }
    #pragma unroll
    for (int r = 0; r < 4; r++) {
        int m = m0 + ty * 4 + r;
        int b = m >> 6, leaf = m & 63;
        int base = (b * NSLOT + leaf) * 512;
        #pragma unroll
        for (int cc = 0; cc < 4; cc++) {
            int col = c0 + tx * 4 + cc;
            float v = acc[r][cc] + bias[col];
            if (col < 512) g_H[base + col] = v;
            else           g_C[base + col - 512] = v;
        }
    }
}

__global__ void init_state(){
    if (blockIdx.x == 0 && threadIdx.x == 0) g_barrier = 0u;
}

// ---------------------------------------------------------------------------
// Full compose for iteration 0: all 63 pairs -> candidate slots 64+j
// ---------------------------------------------------------------------------
__global__ __launch_bounds__(256) void compose_full(
    const float* __restrict__ wcomp, const float* __restrict__ bcomp)
{
    __shared__ float As[128][34];
    __shared__ float Ws[5][8][34];
    const int tid = threadIdx.x;
    const int tx = tid & 7, ty = tid >> 3;
    const int h0 = blockIdx.x * 8;
    const int m0 = blockIdx.y * 128;
    const int M  = BB * 63;   // 4032

    const int lr = tid >> 5, kkld = tid & 31;
    int abase[16];
    #pragma unroll
    for (int t = 0; t < 16; t++) {
        int row = m0 + lr + 8 * t;
        if (row < M) { int b = row / 63; int j = row - b * 63; abase[t] = (b * NSLOT + j) * 512; }
        else abase[t] = -1;
    }

    float2 acc[4][5];
    #pragma unroll
    for (int r = 0; r < 4; r++)
        #pragma unroll
        for (int g = 0; g < 5; g++) acc[r][g] = make_float2(0.f, 0.f);

    for (int k0 = 0; k0 < 1024; k0 += 32) {
        #pragma unroll
        for (int t = 0; t < 16; t++)
            As[lr + 8 * t][kkld] = (abase[t] >= 0) ? g_H[abase[t] + k0 + kkld] : 0.f;
        #pragma unroll
        for (int t = 0; t < 5; t++) {
            int idx = tid + 256 * t;
            int g = idx >> 8, rem = idx & 255, hh = rem >> 5, kk = rem & 31;
            Ws[g][hh][kk] = wcomp[(g * 512 + h0 + hh) * 1024 + k0 + kk];
        }
        __syncthreads();
        #pragma unroll
        for (int k2 = 0; k2 < 16; k2++) {
            float2 wv[5];
            #pragma unroll
            for (int g = 0; g < 5; g++) wv[g] = ((const float2*)Ws[g][tx])[k2];
            #pragma unroll
            for (int r = 0; r < 4; r++) {
                float2 av = ((const float2*)As[ty * 4 + r])[k2];
                #pragma unroll
                for (int g = 0; g < 5; g++) ffma2(acc[r][g], av, wv[g]);
            }
        }
        __syncthreads();
    }

    int hg = h0 + tx;
    float bi  = bcomp[hg],        bfl = bcomp[512 + hg], bfr = bcomp[1024 + hg];
    float bu  = bcomp[1536 + hg], bo  = bcomp[2048 + hg];
    #pragma unroll
    for (int r = 0; r < 4; r++) {
        int row = m0 + ty * 4 + r;
        if (row >= M) continue;
        int b = row / 63, j = row - b * 63;
        int abas = (b * NSLOT + j) * 512;
        int sbas = (b * NSLOT + 64 + j) * 512;
        float cl = g_C[abas + hg], cr = g_C[abas + 512 + hg];
        float vi  = acc[r][0].x + acc[r][0].y + bi;
        float vfl = acc[r][1].x + acc[r][1].y + bfl + 1.f;
        float vfr = acc[r][2].x + acc[r][2].y + bfr + 1.f;
        float vu  = acc[r][3].x + acc[r][3].y + bu;
        float vo  = acc[r][4].x + acc[r][4].y + bo;
        float cn = cl * sigm(vfl) + cr * sigm(vfr) + tanhf(vu) * sigm(vi);
        float hn = sigm(vo) * tanhf(cn);
        g_H[sbas + hg] = hn;
        g_C[sbas + hg] = cn;
    }
}

// cw for all initial pairs (candidate slots 64+j)
__global__ __launch_bounds__(256) void cw_full(const float* __restrict__ q){
    int b = blockIdx.x;
    int warp = threadIdx.x >> 5, lane = threadIdx.x & 31;
    for (int j = warp; j < 63; j += 8) {
        const float* row = &g_H[(b * NSLOT + 64 + j) * 512];
        float s = 0.f;
        #pragma unroll
        for (int t = 0; t < 16; t++) s += row[lane + 32 * t] * q[lane + 32 * t];
        #pragma unroll
        for (int o = 16; o > 0; o >>= 1) s += __shfl_xor_sync(0xffffffffu, s, o);
        if (lane == 0) g_cw0[b * 63 + j] = s;
    }
}

// ---------------------------------------------------------------------------
// Persistent loop: 63 fused {select+compose} phases, ONE grid barrier each.
// Select is computed redundantly per block; merges are slot indirection.
// ---------------------------------------------------------------------------
#define WRES_F   (20*1028)
#define AS_F     (128*66)
#define SMEM_BYTES ((WRES_F + AS_F)*4)

__global__ __launch_bounds__(TPB, 1) void tree_loop(
    const int* __restrict__ length, const float* __restrict__ q,
    const float* __restrict__ wcomp, const float* __restrict__ bcomp,
    float* __restrict__ out)
{
    extern __shared__ float smem[];
    float* Wres = smem;                 // 20 rows (g*4+hh) x 1028 (1024+pad)
    float* As   = smem + WRES_F;        // 128 rows x 66 (64+pad)

    __shared__ unsigned char s_vh[BB][64];   // leaf j -> value slot
    __shared__ unsigned char s_pk[BB][64];   // pair j -> candidate slot
    __shared__ float s_cw[BB][64];           // pair j -> cw
    __shared__ int2  s_fresh[BB];            // pair indices freshened last phase
    __shared__ int4  s_rows[128];            // {baseL, baseR, baseStore, rowid}
    __shared__ int   s_rcnt[BB];
    __shared__ int   s_roff[BB];
    __shared__ int   s_len[BB];
    __shared__ int   s_nrows;

    const int tid = threadIdx.x, blk = blockIdx.x;
    const int tx = tid & 3, ty = tid >> 2;
    const int h0 = blk * 4, hg = h0 + tx;
    const int rowl = tid >> 5, kk2 = tid & 31;

    // resident W slice (20 rows x 1024), loaded once
    for (int idx = tid; idx < 20 * 1024; idx += TPB) {
        int r = idx >> 10, k = idx & 1023;
        Wres[r * 1028 + k] = wcomp[((r >> 2) * 512 + h0 + (r & 3)) * 1024 + k];
    }
    const float qv  = q[hg];
    const float bi  = bcomp[hg],        bfl = bcomp[512 + hg], bfr = bcomp[1024 + hg];
    const float bu  = bcomp[1536 + hg], bo  = bcomp[2048 + hg];

    for (int t = tid; t < BB * 64; t += TPB) {
        int b = t >> 6, j = t & 63;
        s_vh[b][j] = (unsigned char)j;
        s_pk[b][j] = (unsigned char)(64 + j);
        s_cw[b][j] = (j < 63) ? __ldcg(&g_cw0[b * 63 + j]) : -1e9f;
    }
    if (tid < BB) { s_len[tid] = length[tid]; s_fresh[tid] = make_int2(-1, -1); }
    __syncthreads();

    unsigned target = 0;

    for (int i = 0; i < 63; i++) {
        const int n = 63 - i;

        // ---- (a) fold cw partials of pairs freshened last phase ----
        if (i > 0 && tid < 128) {
            int b = tid >> 1;
            int2 fr = s_fresh[b];
            int pidx = (tid & 1) ? fr.y : fr.x;
            if (pidx >= 0) {
                const float* pp = &g_cwp[tid * 128];
                float a0 = 0.f, a1 = 0.f, a2 = 0.f, a3 = 0.f;
                #pragma unroll
                for (int k = 0; k < 128; k += 4) {
                    a0 += __ldcg(pp + k);     a1 += __ldcg(pp + k + 1);
                    a2 += __ldcg(pp + k + 2); a3 += __ldcg(pp + k + 3);
                }
                s_cw[b][pidx] = (a0 + a1) + (a2 + a3);
            }
        }
        __syncthreads();

        // ---- (b) select per batch (redundant, deterministic) ----
        if (tid < BB) {
            int b = tid, len = s_len[b];
            int s;
            if (i + 1 >= len) s = -2;                 // done==0: truncate last leaf
            else if (n == 1) s = 0;
            else {
                float best = -2e9f; int bj = 0;
                for (int j = 0; j < n; j++) {
                    float v = (i + 1 + j < len) ? s_cw[b][j] : -1e9f;
                    if (v > best) { best = v; bj = j; }
                }
                s = bj;
            }
            int2 fr = make_int2(-1, -1);
            if (s >= 0) {
                s_vh[b][s] = s_pk[b][s];              // merge = indirection
                for (int j = s + 1; j < n; j++) s_vh[b][j] = s_vh[b][j + 1];
                for (int j = s; j < n - 1; j++) { s_pk[b][j] = s_pk[b][j + 1]; s_cw[b][j] = s_cw[b][j + 1]; }
                if (i < 62) {
                    if (s >= 1)     fr.x = s - 1;     // post-shift indices
                    if (s <= n - 2) fr.y = s;
                }
            }
            s_fresh[b] = fr;
            s_rcnt[b] = (fr.x >= 0) + (fr.y >= 0);
        }
        __syncthreads();
        if (tid == 0) {
            int acc = 0;
            for (int b = 0; b < BB; b++) { s_roff[b] = acc; acc += s_rcnt[b]; }
            s_nrows = acc;
        }
        __syncthreads();
        if (tid < BB) {
            int b = tid; int2 fr = s_fresh[b]; int o = s_roff[b];
            if (fr.x >= 0) {
                int p = fr.x;
                s_rows[o++] = make_int4((b * NSLOT + s_vh[b][p]) * 512,
                                        (b * NSLOT + s_vh[b][p + 1]) * 512,
                                        (b * NSLOT + s_pk[b][p]) * 512, b * 2 + 0);
            }
            if (fr.y >= 0) {
                int p = fr.y;
                s_rows[o++] = make_int4((b * NSLOT + s_vh[b][p]) * 512,
                                        (b * NSLOT + s_vh[b][p + 1]) * 512,
                                        (b * NSLOT + s_pk[b][p]) * 512, b * 2 + 1);
            }
        }
        __syncthreads();

        // ---- (c) compose fresh pairs (writes go to dead candidate slots) ----
        const int nrows = s_nrows;
        if (nrows > 0) {
            float2 acc[2][5];
            #pragma unroll
            for (int r = 0; r < 2; r++)
                #pragma unroll
                for (int g = 0; g < 5; g++) acc[r][g] = make_float2(0.f, 0.f);

            float2 pv[16];
            #pragma unroll
            for (int t = 0; t < 16; t++) {
                int row = rowl + 8 * t;
                if (row < nrows) {
                    int4 ri = s_rows[row];
                    pv[t] = __ldcg((const float2*)&g_H[ri.x + kk2 * 2]);
                } else pv[t] = make_float2(0.f, 0.f);
            }
            const bool alive = (2 * ty < nrows);

            for (int c = 0; c < 16; c++) {
                __syncthreads();
                #pragma unroll
                for (int t = 0; t < 16; t++)
                    ((float2*)(As + (rowl + 8 * t) * 66))[kk2] = pv[t];
                __syncthreads();
                if (c < 15) {
                    int k0 = (c + 1) * 64;
                    int off = (k0 & 511) + kk2 * 2;
                    #pragma unroll
                    for (int t = 0; t < 16; t++) {
                        int row = rowl + 8 * t;
                        if (row < nrows) {
                            int4 ri = s_rows[row];
                            int basep = (k0 < 512) ? ri.x : ri.y;
                            pv[t] = __ldcg((const float2*)&g_H[basep + off]);
                        } else pv[t] = make_float2(0.f, 0.f);
                    }
                }
                if (alive) {
                    #pragma unroll
                    for (int k2 = 0; k2 < 32; k2++) {
                        float2 wv[5];
                        #pragma unroll
                        for (int g = 0; g < 5; g++)
                            wv[g] = ((const float2*)(Wres + (g * 4 + tx) * 1028))[c * 32 + k2];
                        #pragma unroll
                        for (int r = 0; r < 2; r++) {
                            float2 av = ((const float2*)(As + (ty * 2 + r) * 66))[k2];
                            #pragma unroll
                            for (int g = 0; g < 5; g++) ffma2(acc[r][g], av, wv[g]);
                        }
                    }
                }
            }

            #pragma unroll
            for (int r = 0; r < 2; r++) {
                int row = ty * 2 + r;
                float p = 0.f;
                if (row < nrows) {
                    int4 ri = s_rows[row];
                    float cl = __ldcg(&g_C[ri.x + hg]);
                    float cr = __ldcg(&g_C[ri.y + hg]);
                    float vi  = acc[r][0].x + acc[r][0].y + bi;
                    float vfl = acc[r][1].x + acc[r][1].y + bfl + 1.f;
                    float vfr = acc[r][2].x + acc[r][2].y + bfr + 1.f;
                    float vu  = acc[r][3].x + acc[r][3].y + bu;
                    float vo  = acc[r][4].x + acc[r][4].y + bo;
                    float cn = cl * sigm(vfl) + cr * sigm(vfr) + tanhf(vu) * sigm(vi);
                    float hn = sigm(vo) * tanhf(cn);
                    g_H[ri.z + hg] = hn;
                    g_C[ri.z + hg] = cn;
                    p = hn * qv;
                }
                p += __shfl_xor_sync(0xffffffffu, p, 1);
                p += __shfl_xor_sync(0xffffffffu, p, 2);
                if (row < nrows && tx == 0) g_cwp[s_rows[row].w * 128 + blk] = p;
            }
        }
        target += GRID; grid_barrier(target);
    }

    // ---- output: leaf 0's value slot ----
    if (blk < BB) {
        int base = (blk * NSLOT + s_vh[blk][0]) * 512;
        out[blk * 512 + tid]                  = __ldcg(&g_H[base + tid]);
        out[blk * 512 + 256 + tid]            = __ldcg(&g_H[base + 256 + tid]);
        out[BB * 512 + blk * 512 + tid]       = __ldcg(&g_C[base + tid]);
        out[BB * 512 + blk * 512 + 256 + tid] = __ldcg(&g_C[base + 256 + tid]);
    }
}

// ---------------------------------------------------------------------------
extern "C" void kernel_launch(void* const* d_in, const int* in_sizes, int n_in,
                              void* d_out, int out_size)
{
    const float* x      = (const float*)d_in[0];
    const int*   length = (const int*)  d_in[1];
    const float* w_word = (const float*)d_in[2];
    const float* b_word = (const float*)d_in[3];
    const float* w_comp = (const float*)d_in[4];
    const float* b_comp = (const float*)d_in[5];
    const float* q      = (const float*)d_in[6];
    float* out = (float*)d_out;

    static int smem_set = 0;
    if (!smem_set) {
        cudaFuncSetAttribute(tree_loop, cudaFuncAttributeMaxDynamicSharedMemorySize,
                             SMEM_BYTES);
        smem_set = 1;
    }

    word_gemm<<<dim3(16, 64), 256>>>(x, w_word, b_word);
    init_state<<<1, 32>>>();
    compose_full<<<dim3(64, 32), 256>>>(w_comp, b_comp);
    cw_full<<<BB, 256>>>(q);
    tree_loop<<<GRID, TPB, SMEM_BYTES>>>(length, q, w_comp, b_comp, out);
}

// round 5
// speedup vs baseline: 1.1156x; 1.1156x over previous
#include <cuda_runtime.h>
#include <math.h>

#define BB 64
#define LL 64
#define GRID 128
#define TPB 256
#define NSLOT 128                    // 64 leaf slots + 63 candidate slots + spare
#define NST (BB*NSLOT*512)           // 16 MB per array

__device__ float g_H[NST];           // unified value/candidate storage (h)
__device__ float g_C[NST];           // unified value/candidate storage (c)
__device__ float g_cwp[128*128];     // cw partials: [rowid][block]
__device__ float g_cw0[BB*63];       // initial pair cw
__device__ unsigned g_barrier;

__device__ __forceinline__ float sigm(float x){ return 1.0f/(1.0f+expf(-x)); }

// packed fp32x2 FMA: 2 MACs/instr (scalar FFMA is half-rate on sm_103a)
__device__ __forceinline__ void ffma2(float2 &acc, float2 a, float2 b){
    asm("fma.rn.f32x2 %0, %1, %2, %0;"
        : "+l"(reinterpret_cast<unsigned long long&>(acc))
        : "l"(reinterpret_cast<unsigned long long&>(a)),
          "l"(reinterpret_cast<unsigned long long&>(b)));
}

// release/acquire grid barrier (all GRID blocks co-resident: 1 block/SM)
__device__ __forceinline__ void grid_barrier(unsigned target){
    __syncthreads();
    if (threadIdx.x == 0){
        asm volatile("red.release.gpu.global.add.u32 [%0], 1;"
                     :: "l"(&g_barrier) : "memory");
        unsigned v;
        do {
            asm volatile("ld.acquire.gpu.global.u32 %0, [%1];"
                         : "=r"(v) : "l"(&g_barrier) : "memory");
        } while (v < target);
    }
    __syncthreads();
}

// ---------------------------------------------------------------------------
// Word GEMM: state = x @ w_word^T + b_word -> leaf slots 0..63
// ---------------------------------------------------------------------------
__global__ __launch_bounds__(256) void word_gemm(
    const float* __restrict__ x, const float* __restrict__ w,
    const float* __restrict__ bias)
{
    __shared__ float As[64][33];
    __shared__ float Ws[64][33];
    int tid = threadIdx.x;
    int tx = tid & 15, ty = tid >> 4;
    int m0 = blockIdx.y * 64;
    int c0 = blockIdx.x * 64;
    float acc[4][4] = {};

    for (int k0 = 0; k0 < 512; k0 += 32) {
        #pragma unroll
        for (int t = tid; t < 64 * 32; t += 256) {
            int r = t >> 5, kk = t & 31;
            As[r][kk] = x[(m0 + r) * 512 + k0 + kk];
            Ws[r][kk] = w[(c0 + r) * 512 + k0 + kk];
        }
        __syncthreads();
        #pragma unroll
        for (int kk = 0; kk < 32; kk++) {
            float a[4], b[4];
            #pragma unroll
            for (int r = 0; r < 4; r++) a[r] = As[ty * 4 + r][kk];
            #pragma unroll
            for (int cc = 0; cc < 4; cc++) b[cc] = Ws[tx * 4 + cc][kk];
            #pragma unroll
            for (int r = 0; r < 4; r++)
                #pragma unroll
                for (int cc = 0; cc < 4; cc++)
                    acc[r][cc] += a[r] * b[cc];
        }
        __syncthreads();
    }
    #pragma unroll
    for (int r = 0; r < 4; r++) {
        int m = m0 + ty * 4 + r;
        int b = m >> 6, leaf = m & 63;
        int base = (b * NSLOT + leaf) * 512;
        #pragma unroll
        for (int cc = 0; cc < 4; cc++) {
            int col = c0 + tx * 4 + cc;
            float v = acc[r][cc] + bias[col];
            if (col < 512) g_H[base + col] = v;
            else           g_C[base + col - 512] = v;
        }
    }
}

__global__ void init_state(){
    if (blockIdx.x == 0 && threadIdx.x == 0) g_barrier = 0u;
}

// ---------------------------------------------------------------------------
// Full compose for iteration 0: all 63 pairs -> candidate slots 64+j
// ---------------------------------------------------------------------------
__global__ __launch_bounds__(256) void compose_full(
    const float* __restrict__ wcomp, const float* __restrict__ bcomp)
{
    __shared__ float As[128][34];
    __shared__ float Ws[5][8][34];
    const int tid = threadIdx.x;
    const int tx = tid & 7, ty = tid >> 3;
    const int h0 = blockIdx.x * 8;
    const int m0 = blockIdx.y * 128;
    const int M  = BB * 63;   // 4032

    const int lr = tid >> 5, kkld = tid & 31;
    int abase[16];
    #pragma unroll
    for (int t = 0; t < 16; t++) {
        int row = m0 + lr + 8 * t;
        if (row < M) { int b = row / 63; int j = row - b * 63; abase[t] = (b * NSLOT + j) * 512; }
        else abase[t] = -1;
    }

    float2 acc[4][5];
    #pragma unroll
    for (int r = 0; r < 4; r++)
        #pragma unroll
        for (int g = 0; g < 5; g++) acc[r][g] = make_float2(0.f, 0.f);

    for (int k0 = 0; k0 < 1024; k0 += 32) {
        #pragma unroll
        for (int t = 0; t < 16; t++)
            As[lr + 8 * t][kkld] = (abase[t] >= 0) ? g_H[abase[t] + k0 + kkld] : 0.f;
        #pragma unroll
        for (int t = 0; t < 5; t++) {
            int idx = tid + 256 * t;
            int g = idx >> 8, rem = idx & 255, hh = rem >> 5, kk = rem & 31;
            Ws[g][hh][kk] = wcomp[(g * 512 + h0 + hh) * 1024 + k0 + kk];
        }
        __syncthreads();
        #pragma unroll
        for (int k2 = 0; k2 < 16; k2++) {
            float2 wv[5];
            #pragma unroll
            for (int g = 0; g < 5; g++) wv[g] = ((const float2*)Ws[g][tx])[k2];
            #pragma unroll
            for (int r = 0; r < 4; r++) {
                float2 av = ((const float2*)As[ty * 4 + r])[k2];
                #pragma unroll
                for (int g = 0; g < 5; g++) ffma2(acc[r][g], av, wv[g]);
            }
        }
        __syncthreads();
    }

    int hg = h0 + tx;
    float bi  = bcomp[hg],        bfl = bcomp[512 + hg], bfr = bcomp[1024 + hg];
    float bu  = bcomp[1536 + hg], bo  = bcomp[2048 + hg];
    #pragma unroll
    for (int r = 0; r < 4; r++) {
        int row = m0 + ty * 4 + r;
        if (row >= M) continue;
        int b = row / 63, j = row - b * 63;
        int abas = (b * NSLOT + j) * 512;
        int sbas = (b * NSLOT + 64 + j) * 512;
        float cl = g_C[abas + hg], cr = g_C[abas + 512 + hg];
        float vi  = acc[r][0].x + acc[r][0].y + bi;
        float vfl = acc[r][1].x + acc[r][1].y + bfl + 1.f;
        float vfr = acc[r][2].x + acc[r][2].y + bfr + 1.f;
        float vu  = acc[r][3].x + acc[r][3].y + bu;
        float vo  = acc[r][4].x + acc[r][4].y + bo;
        float cn = cl * sigm(vfl) + cr * sigm(vfr) + tanhf(vu) * sigm(vi);
        float hn = sigm(vo) * tanhf(cn);
        g_H[sbas + hg] = hn;
        g_C[sbas + hg] = cn;
    }
}

// cw for all initial pairs (candidate slots 64+j)
__global__ __launch_bounds__(256) void cw_full(const float* __restrict__ q){
    int b = blockIdx.x;
    int warp = threadIdx.x >> 5, lane = threadIdx.x & 31;
    for (int j = warp; j < 63; j += 8) {
        const float* row = &g_H[(b * NSLOT + 64 + j) * 512];
        float s = 0.f;
        #pragma unroll
        for (int t = 0; t < 16; t++) s += row[lane + 32 * t] * q[lane + 32 * t];
        #pragma unroll
        for (int o = 16; o > 0; o >>= 1) s += __shfl_xor_sync(0xffffffffu, s, o);
        if (lane == 0) g_cw0[b * 63 + j] = s;
    }
}

// ---------------------------------------------------------------------------
// Persistent loop: 63 fused {fold+select+compose} phases, ONE grid barrier each.
// Select is computed redundantly per block; merges are slot indirection.
// As is double-buffered -> one __syncthreads per k-chunk, stores overlap FMA.
// ---------------------------------------------------------------------------
#define WRES_F   (20*1028)
#define ASB_F    (128*66)
#define SMEM_BYTES ((WRES_F + 2*ASB_F)*4)

__global__ __launch_bounds__(TPB, 1) void tree_loop(
    const int* __restrict__ length, const float* __restrict__ q,
    const float* __restrict__ wcomp, const float* __restrict__ bcomp,
    float* __restrict__ out)
{
    extern __shared__ float smem[];
    float* Wres = smem;                        // 20 rows (g*4+hh) x 1028
    float* Asb0 = smem + WRES_F;               // 128 x 66 (buffer 0)
    float* Asb1 = smem + WRES_F + ASB_F;       // 128 x 66 (buffer 1)

    __shared__ unsigned char s_vh[BB][64];     // leaf j -> value slot
    __shared__ unsigned char s_pk[BB][64];     // pair j -> candidate slot
    __shared__ float s_cw[BB][64];             // pair j -> cw
    __shared__ int2  s_fresh[BB];              // pair indices freshened last phase
    __shared__ int4  s_rows[128];              // {baseL, baseR, baseStore, rowid}
    __shared__ int   s_rcnt[BB];
    __shared__ int   s_roff[BB];
    __shared__ int   s_len[BB];
    __shared__ int   s_nrows;

    const int tid = threadIdx.x, blk = blockIdx.x;
    const int tx = tid & 3, ty = tid >> 2;
    const int h0 = blk * 4, hg = h0 + tx;
    const int lane = tid & 31, warp = tid >> 5;
    const int rowl = tid >> 5, kk2 = tid & 31;

    // resident W slice (20 rows x 1024), loaded once
    for (int idx = tid; idx < 20 * 1024; idx += TPB) {
        int r = idx >> 10, k = idx & 1023;
        Wres[r * 1028 + k] = wcomp[((r >> 2) * 512 + h0 + (r & 3)) * 1024 + k];
    }
    const float qv  = q[hg];
    const float bi  = bcomp[hg],        bfl = bcomp[512 + hg], bfr = bcomp[1024 + hg];
    const float bu  = bcomp[1536 + hg], bo  = bcomp[2048 + hg];

    for (int t = tid; t < BB * 64; t += TPB) {
        int b = t >> 6, j = t & 63;
        s_vh[b][j] = (unsigned char)j;
        s_pk[b][j] = (unsigned char)(64 + j);
        s_cw[b][j] = (j < 63) ? __ldcg(&g_cw0[b * 63 + j]) : -1e9f;
    }
    if (tid < BB) { s_len[tid] = length[tid]; s_fresh[tid] = make_int2(-1, -1); }
    __syncthreads();

    unsigned target = 0;

    for (int i = 0; i < 63; i++) {
        const int n = 63 - i;

        // ---- (a) fold cw partials of pairs freshened last phase ----
        // warp w handles rowids w, w+8, ...: 128 partials = 32 lanes x float4
        if (i > 0) {
            #pragma unroll
            for (int rr = 0; rr < 16; rr++) {
                int rid = warp + 8 * rr;
                int b = rid >> 1;
                int2 fr = s_fresh[b];
                int pidx = (rid & 1) ? fr.y : fr.x;
                if (pidx >= 0) {
                    float4 v = __ldcg((const float4*)&g_cwp[rid * 128 + lane * 4]);
                    float s = (v.x + v.y) + (v.z + v.w);
                    #pragma unroll
                    for (int o = 16; o > 0; o >>= 1) s += __shfl_xor_sync(0xffffffffu, s, o);
                    if (lane == 0) s_cw[b][pidx] = s;
                }
            }
        }
        __syncthreads();

        // ---- (b) select per batch (redundant, deterministic) ----
        if (tid < BB) {
            int b = tid, len = s_len[b];
            int s;
            if (i + 1 >= len) s = -2;                 // done==0: truncate last leaf
            else if (n == 1) s = 0;
            else {
                float best = -2e9f; int bj = 0;
                for (int j = 0; j < n; j++) {
                    float v = (i + 1 + j < len) ? s_cw[b][j] : -1e9f;
                    if (v > best) { best = v; bj = j; }
                }
                s = bj;
            }
            int2 fr = make_int2(-1, -1);
            if (s >= 0) {
                s_vh[b][s] = s_pk[b][s];              // merge = indirection
                for (int j = s + 1; j < n; j++) s_vh[b][j] = s_vh[b][j + 1];
                for (int j = s; j < n - 1; j++) { s_pk[b][j] = s_pk[b][j + 1]; s_cw[b][j] = s_cw[b][j + 1]; }
                if (i < 62) {
                    if (s >= 1)     fr.x = s - 1;     // post-shift indices
                    if (s <= n - 2) fr.y = s;
                }
            }
            s_fresh[b] = fr;
            s_rcnt[b] = (fr.x >= 0) + (fr.y >= 0);
        }
        __syncthreads();
        if (tid == 0) {
            int acc = 0;
            for (int b = 0; b < BB; b++) { s_roff[b] = acc; acc += s_rcnt[b]; }
            s_nrows = acc;
        }
        __syncthreads();
        if (tid < BB) {
            int b = tid; int2 fr = s_fresh[b]; int o = s_roff[b];
            if (fr.x >= 0) {
                int p = fr.x;
                s_rows[o++] = make_int4((b * NSLOT + s_vh[b][p]) * 512,
                                        (b * NSLOT + s_vh[b][p + 1]) * 512,
                                        (b * NSLOT + s_pk[b][p]) * 512, b * 2 + 0);
            }
            if (fr.y >= 0) {
                int p = fr.y;
                s_rows[o++] = make_int4((b * NSLOT + s_vh[b][p]) * 512,
                                        (b * NSLOT + s_vh[b][p + 1]) * 512,
                                        (b * NSLOT + s_pk[b][p]) * 512, b * 2 + 1);
            }
        }
        __syncthreads();

        // ---- (c) compose fresh pairs (writes go to dead candidate slots) ----
        const int nrows = s_nrows;
        if (nrows > 0) {
            const int T = (nrows + 7) >> 3;    // active row-groups (rowl stride 8)

            float2 acc[2][5];
            #pragma unroll
            for (int r = 0; r < 2; r++)
                #pragma unroll
                for (int g = 0; g < 5; g++) acc[r][g] = make_float2(0.f, 0.f);

            const bool alive = (2 * ty < nrows);

            // preload chunk 0 -> buffer 0
            float2 pvn[16];
            #pragma unroll
            for (int t = 0; t < 16; t++) {
                int row = rowl + 8 * t;
                pvn[t] = (row < nrows)
                       ? __ldcg((const float2*)&g_H[s_rows[row].x + kk2 * 2])
                       : make_float2(0.f, 0.f);
            }
            #pragma unroll
            for (int t = 0; t < 16; t++)
                if (t < T) ((float2*)(Asb0 + (rowl + 8 * t) * 66))[kk2] = pvn[t];
            __syncthreads();

            for (int c = 0; c < 16; c++) {
                // issue loads for chunk c+1 (arrive during FMA burst)
                if (c < 15) {
                    int k0 = (c + 1) * 64;
                    int off = (k0 & 511) + kk2 * 2;
                    #pragma unroll
                    for (int t = 0; t < 16; t++) {
                        int row = rowl + 8 * t;
                        if (row < nrows) {
                            int4 ri = s_rows[row];
                            int basep = (k0 < 512) ? ri.x : ri.y;
                            pvn[t] = __ldcg((const float2*)&g_H[basep + off]);
                        } else pvn[t] = make_float2(0.f, 0.f);
                    }
                }
                // FMA on current buffer
                const float* Asc = (c & 1) ? Asb1 : Asb0;
                if (alive) {
                    #pragma unroll
                    for (int k2 = 0; k2 < 32; k2++) {
                        float2 wv[5];
                        #pragma unroll
                        for (int g = 0; g < 5; g++)
                            wv[g] = ((const float2*)(Wres + (g * 4 + tx) * 1028))[c * 32 + k2];
                        #pragma unroll
                        for (int r = 0; r < 2; r++) {
                            float2 av = ((const float2*)(Asc + (ty * 2 + r) * 66))[k2];
                            #pragma unroll
                            for (int g = 0; g < 5; g++) ffma2(acc[r][g], av, wv[g]);
                        }
                    }
                }
                // store chunk c+1 into the OTHER buffer (its previous readers
                // finished at the sync that ended iteration c-1)
                if (c < 15) {
                    float* Asn = (c & 1) ? Asb0 : Asb1;
                    #pragma unroll
                    for (int t = 0; t < 16; t++)
                        if (t < T) ((float2*)(Asn + (rowl + 8 * t) * 66))[kk2] = pvn[t];
                }
                __syncthreads();
            }

            #pragma unroll
            for (int r = 0; r < 2; r++) {
                int row = ty * 2 + r;
                float p = 0.f;
                if (row < nrows) {
                    int4 ri = s_rows[row];
                    float cl = __ldcg(&g_C[ri.x + hg]);
                    float cr = __ldcg(&g_C[ri.y + hg]);
                    float vi  = acc[r][0].x + acc[r][0].y + bi;
                    float vfl = acc[r][1].x + acc[r][1].y + bfl + 1.f;
                    float vfr = acc[r][2].x + acc[r][2].y + bfr + 1.f;
                    float vu  = acc[r][3].x + acc[r][3].y + bu;
                    float vo  = acc[r][4].x + acc[r][4].y + bo;
                    float cn = cl * sigm(vfl) + cr * sigm(vfr) + tanhf(vu) * sigm(vi);
                    float hn = sigm(vo) * tanhf(cn);
                    g_H[ri.z + hg] = hn;
                    g_C[ri.z + hg] = cn;
                    p = hn * qv;
                }
                p += __shfl_xor_sync(0xffffffffu, p, 1);
                p += __shfl_xor_sync(0xffffffffu, p, 2);
                if (row < nrows && tx == 0) g_cwp[s_rows[row].w * 128 + blk] = p;
            }
        }
        target += GRID; grid_barrier(target);
    }

    // ---- output: leaf 0's value slot ----
    if (blk < BB) {
        int base = (blk * NSLOT + s_vh[blk][0]) * 512;
        out[blk * 512 + tid]                  = __ldcg(&g_H[base + tid]);
        out[blk * 512 + 256 + tid]            = __ldcg(&g_H[base + 256 + tid]);
        out[BB * 512 + blk * 512 + tid]       = __ldcg(&g_C[base + tid]);
        out[BB * 512 + blk * 512 + 256 + tid] = __ldcg(&g_C[base + 256 + tid]);
    }
}

// ---------------------------------------------------------------------------
extern "C" void kernel_launch(void* const* d_in, const int* in_sizes, int n_in,
                              void* d_out, int out_size)
{
    const float* x      = (const float*)d_in[0];
    const int*   length = (const int*)  d_in[1];
    const float* w_word = (const float*)d_in[2];
    const float* b_word = (const float*)d_in[3];
    const float* w_comp = (const float*)d_in[4];
    const float* b_comp = (const float*)d_in[5];
    const float* q      = (const float*)d_in[6];
    float* out = (float*)d_out;

    static int smem_set = 0;
    if (!smem_set) {
        cudaFuncSetAttribute(tree_loop, cudaFuncAttributeMaxDynamicSharedMemorySize,
                             SMEM_BYTES);
        smem_set = 1;
    }

    word_gemm<<<dim3(16, 64), 256>>>(x, w_word, b_word);
    init_state<<<1, 32>>>();
    compose_full<<<dim3(64, 32), 256>>>(w_comp, b_comp);
    cw_full<<<BB, 256>>>(q);
    tree_loop<<<GRID, TPB, SMEM_BYTES>>>(length, q, w_comp, b_comp, out);
}